// round 5
// baseline (speedup 1.0000x reference)
#include <cuda_runtime.h>

#define NGRID 48
#define N3 (NGRID * NGRID * NGRID)
#define NATOMS_MAX 1024
#define TILE 4
#define TILES_X (NGRID / TILE)        // 12
#define NBLOCKS (TILES_X * TILES_X)   // 144
#define NTHREADS 512

// r^2 exactly as the reference: float32((1.5*1.52)**2), product in double.
__device__ __forceinline__ float ref_r2() {
    const double r = 1.5 * 1.52;
    return (float)(r * r);
}

__global__ __launch_bounds__(NTHREADS)
void wat_mask_kernel(const float* __restrict__ vecs, int n_atoms,
                     float* __restrict__ out) {
    __shared__ float4 satom[NATOMS_MAX];  // compacted culled atoms
    __shared__ int scnt[32];              // per (warp, batch) match counts

    const float R2 = ref_r2();            // ~5.1984
    const float RM = 2.2802f;             // > sqrt(R2): conservative margin

    const int bx = blockIdx.x % TILES_X;
    const int by = blockIdx.x / TILES_X;
    const int x0 = bx * TILE;
    const int y0 = by * TILE;

    const int tid  = threadIdx.x;
    const int wid  = tid >> 5;            // 16 warps
    const int lane = tid & 31;

    // ---- Phase 1a: load both atom batches up front (max MLP), cull vs AABB.
    const int i0 = tid;
    const int i1 = tid + NTHREADS;
    const bool v0 = (i0 < n_atoms);
    const bool v1 = (i1 < n_atoms);
    float ax0 = 0.f, ay0 = 0.f, az0 = 0.f;
    float ax1 = 0.f, ay1 = 0.f, az1 = 0.f;
    if (v0) { ax0 = vecs[3*i0]; ay0 = vecs[3*i0+1]; az0 = vecs[3*i0+2]; }
    if (v1) { ax1 = vecs[3*i1]; ay1 = vecs[3*i1+1]; az1 = vecs[3*i1+2]; }

    const float xmin = 0.5f * (float)x0 - RM;
    const float xmax = 0.5f * (float)(x0 + TILE - 1) + RM;
    const float ymin = 0.5f * (float)y0 - RM;
    const float ymax = 0.5f * (float)(y0 + TILE - 1) + RM;

    const bool match0 = v0 && ax0 >= xmin && ax0 <= xmax
                           && ay0 >= ymin && ay0 <= ymax;
    const bool match1 = v1 && ax1 >= xmin && ax1 <= xmax
                           && ay1 >= ymin && ay1 <= ymax;
    const unsigned m0 = __ballot_sync(0xffffffffu, match0);
    const unsigned m1 = __ballot_sync(0xffffffffu, match1);
    if (lane == 0) {
        scnt[2 * wid]     = __popc(m0);
        scnt[2 * wid + 1] = __popc(m1);
    }
    __syncthreads();

    // ---- Phase 1b: every warp redundantly scans the 32 counts (no atomics).
    const int c_l = scnt[lane];
    int inc = c_l;
    #pragma unroll
    for (int off = 1; off < 32; off <<= 1) {
        const int t = __shfl_up_sync(0xffffffffu, inc, off);
        if (lane >= off) inc += t;
    }
    const int total = __shfl_sync(0xffffffffu, inc, 31);
    const int exc   = inc - c_l;                      // exclusive prefix
    const int base0 = __shfl_sync(0xffffffffu, exc, 2 * wid);
    const int base1 = __shfl_sync(0xffffffffu, exc, 2 * wid + 1);

    const unsigned lt = (1u << lane) - 1u;
    if (match0) satom[base0 + __popc(m0 & lt)] = make_float4(ax0, ay0, az0, 0.f);
    if (match1) satom[base1 + __popc(m1 & lt)] = make_float4(ax1, ay1, az1, 0.f);
    __syncthreads();

    // ---- Phase 2: one warp per column. For each atom with sxy < R2, every
    // passing z satisfies |2*az - z| < 4.5604 (exact-test bound + fp margin),
    // i.e. z is one of the 10 integers (floor(t), floor(t)+10], t=2az-4.5604.
    // Evaluate the exact reference-rounded test at all 10 candidates,
    // branchlessly, with full ILP (no sqrt, no walk loops, no divergence).
    const int cx = wid >> 2;
    const int cy = wid & 3;
    const float px = 0.5f * (float)(x0 + cx);         // exact in fp32
    const float py = 0.5f * (float)(y0 + cy);

    unsigned long long mask = 0ull;
    for (int j = lane; j < total; j += 32) {
        const float4 a = satom[j];
        const float dx  = __fsub_rn(a.x, px);
        const float dy  = __fsub_rn(a.y, py);
        const float sxy = __fadd_rn(__fmul_rn(dx, dx), __fmul_rn(dy, dy));
        if (sxy < R2) {
            const float az = a.z;
            // 2*az is exact (az <= 24); window start with conservative margin.
            const float t  = __fsub_rn(__fadd_rn(az, az), 4.5604f);
            const int   z0 = (int)floorf(t);
            #pragma unroll
            for (int k = 1; k <= 10; ++k) {
                const int zi = z0 + k;
                const float dz = __fsub_rn(az, 0.5f * (float)zi);
                const float d2 = __fadd_rn(sxy, __fmul_rn(dz, dz));
                if (d2 < R2 && (unsigned)zi < (unsigned)NGRID)
                    mask |= 1ull << zi;
            }
        }
    }
    const unsigned lo = __reduce_or_sync(0xffffffffu, (unsigned)mask);
    const unsigned hi = __reduce_or_sync(0xffffffffu, (unsigned)(mask >> 32));
    mask = (unsigned long long)lo | ((unsigned long long)hi << 32);

    // ---- Epilogue: warp-direct stores, no barrier. Lanes 0-11 write ch0,
    // lanes 12-23 write ch1 (12 float4 each = 192B contiguous per channel).
    if (lane < 24) {
        const int ch = (lane >= 12);
        const int zq = ch ? lane - 12 : lane;
        const unsigned bits = (unsigned)(mask >> (4 * zq)) & 0xFu;

        const float on  = ch ? 25.0f : 1.0f;
        const float off = ch ? 1.0f  : 0.0f;
        float4 v;
        v.x = (bits & 1u) ? on : off;
        v.y = (bits & 2u) ? on : off;
        v.z = (bits & 4u) ? on : off;
        v.w = (bits & 8u) ? on : off;

        const int gx = x0 + cx;
        const int gy = y0 + cy;
        const int idx = ch * N3 + (gx * NGRID + gy) * NGRID + 4 * zq;
        *reinterpret_cast<float4*>(out + idx) = v;
    }
}

extern "C" void kernel_launch(void* const* d_in, const int* in_sizes, int n_in,
                              void* d_out, int out_size) {
    const float* vecs = (const float*)d_in[0];
    const int n_atoms = in_sizes[0] / 3;
    float* out = (float*)d_out;
    wat_mask_kernel<<<NBLOCKS, NTHREADS>>>(vecs, n_atoms, out);
}

// round 6
// speedup vs baseline: 1.0870x; 1.0870x over previous
#include <cuda_runtime.h>

#define NGRID 48
#define N3 (NGRID * NGRID * NGRID)
#define NATOMS_MAX 1024
#define TILE 4
#define TILES_X (NGRID / TILE)        // 12
#define NBLOCKS (TILES_X * TILES_X)   // 144
#define NTHREADS 1024

// r^2 exactly as the reference: float32((1.5*1.52)**2), product in double.
__device__ __forceinline__ float ref_r2() {
    const double r = 1.5 * 1.52;
    return (float)(r * r);
}

__global__ __launch_bounds__(NTHREADS)
void wat_mask_kernel(const float* __restrict__ vecs, int n_atoms,
                     float* __restrict__ out) {
    __shared__ float4 satom[NATOMS_MAX];  // compacted culled atoms
    __shared__ int scnt[32];              // per-warp match counts

    const float R2 = ref_r2();            // ~5.1984
    const float RM = 2.2802f;             // > sqrt(R2): conservative margin

    const int bx = blockIdx.x % TILES_X;
    const int by = blockIdx.x / TILES_X;
    const int x0 = bx * TILE;
    const int y0 = by * TILE;

    const int tid  = threadIdx.x;
    const int wid  = tid >> 5;            // 32 warps
    const int lane = tid & 31;

    // ---- Phase 1: one atom per thread, cull vs expanded tile AABB.
    const bool v0 = (tid < n_atoms);
    float ax = 0.f, ay = 0.f, az = 0.f;
    if (v0) { ax = vecs[3*tid]; ay = vecs[3*tid+1]; az = vecs[3*tid+2]; }

    const float xmin = 0.5f * (float)x0 - RM;
    const float xmax = 0.5f * (float)(x0 + TILE - 1) + RM;
    const float ymin = 0.5f * (float)y0 - RM;
    const float ymax = 0.5f * (float)(y0 + TILE - 1) + RM;

    const bool match = v0 && ax >= xmin && ax <= xmax
                          && ay >= ymin && ay <= ymax;
    const unsigned m = __ballot_sync(0xffffffffu, match);
    if (lane == 0) scnt[wid] = __popc(m);
    __syncthreads();

    // ---- Offsets via REDUX (no serial scan): base_w = sum of counts < wid.
    const int c_l   = scnt[lane];
    const int base  = __reduce_add_sync(0xffffffffu, (lane < wid) ? c_l : 0);
    const int total = __reduce_add_sync(0xffffffffu, c_l);

    if (match) {
        const int p = base + __popc(m & ((1u << lane) - 1u));
        satom[p] = make_float4(ax, ay, az, 0.f);
    }
    __syncthreads();

    // Warps 16-31 are done (they participated in both barriers).
    if (wid >= TILE * TILE) return;

    // ---- Phase 2: one warp per column. Passing z-set per atom is a
    // contiguous interval (RN-monotone); sqrt estimate (+/-1 slack) then
    // exact reference-rounded walk-in at the endpoints.
    const int cx = wid >> 2;
    const int cy = wid & 3;
    const float px = 0.5f * (float)(x0 + cx);         // exact in fp32
    const float py = 0.5f * (float)(y0 + cy);

    unsigned long long mask = 0ull;
    for (int j = lane; j < total; j += 32) {
        const float4 a = satom[j];
        const float dx  = __fsub_rn(a.x, px);
        const float dy  = __fsub_rn(a.y, py);
        const float sxy = __fadd_rn(__fmul_rn(dx, dx), __fmul_rn(dy, dy));
        if (sxy >= R2) continue;          // rigorous: RN(sxy+dz^2) >= sxy

        const float azj = a.z;
        const float rad = sqrtf(__fsub_rn(R2, sxy));
        int zl = (int)ceilf((azj - rad) * 2.0f) - 1;
        int zh = (int)floorf((azj + rad) * 2.0f) + 1;
        zl = max(zl, 0);
        zh = min(zh, NGRID - 1);

        while (zl <= zh) {                // exact walk-in, low end
            const float dz = __fsub_rn(azj, 0.5f * (float)zl);
            if (__fadd_rn(sxy, __fmul_rn(dz, dz)) < R2) break;
            ++zl;
        }
        while (zh >= zl) {                // exact walk-in, high end
            const float dz = __fsub_rn(azj, 0.5f * (float)zh);
            if (__fadd_rn(sxy, __fmul_rn(dz, dz)) < R2) break;
            --zh;
        }
        if (zl <= zh) {
            const int len = zh - zl + 1;
            const unsigned long long run =
                (len >= 64) ? ~0ull : ((1ull << len) - 1ull);
            mask |= run << zl;
        }
    }
    const unsigned lo = __reduce_or_sync(0xffffffffu, (unsigned)mask);
    const unsigned hi = __reduce_or_sync(0xffffffffu, (unsigned)(mask >> 32));
    mask = (unsigned long long)lo | ((unsigned long long)hi << 32);

    // ---- Epilogue: warp-direct stores, no barrier. Lanes 0-11 write ch0,
    // lanes 12-23 write ch1 (12 float4 each = 192B contiguous per channel).
    if (lane < 24) {
        const int ch = (lane >= 12);
        const int zq = ch ? lane - 12 : lane;
        const unsigned bits = (unsigned)(mask >> (4 * zq)) & 0xFu;

        const float on  = ch ? 25.0f : 1.0f;
        const float off = ch ? 1.0f  : 0.0f;
        float4 v;
        v.x = (bits & 1u) ? on : off;
        v.y = (bits & 2u) ? on : off;
        v.z = (bits & 4u) ? on : off;
        v.w = (bits & 8u) ? on : off;

        const int gx = x0 + cx;
        const int gy = y0 + cy;
        const int idx = ch * N3 + (gx * NGRID + gy) * NGRID + 4 * zq;
        *reinterpret_cast<float4*>(out + idx) = v;
    }
}

extern "C" void kernel_launch(void* const* d_in, const int* in_sizes, int n_in,
                              void* d_out, int out_size) {
    const float* vecs = (const float*)d_in[0];
    const int n_atoms = in_sizes[0] / 3;
    float* out = (float*)d_out;
    wat_mask_kernel<<<NBLOCKS, NTHREADS>>>(vecs, n_atoms, out);
}